// round 1
// baseline (speedup 1.0000x reference)
#include <cuda_runtime.h>
#include <cuda_bf16.h>

#define D_MODEL 1024
#define FF_DIM  1024
#define BATCH   8
#define SEQ     2048
#define M_TOTAL (BATCH * SEQ)      // 16384
#define ATTN_SCALE 0.03125f

// ---------------- scratch (device globals; no runtime allocation) ----------
__device__ float g_q[M_TOTAL * FF_DIM];                 // 64 MB
__device__ float g_k[M_TOTAL * FF_DIM];                 // 64 MB
__device__ float g_v[M_TOTAL * FF_DIM];                 // 64 MB
__device__ float g_s[(size_t)BATCH * SEQ * SEQ];        // 128 MB

// ---------------------------------------------------------------------------
// Tiled SGEMM (NT): C[m,n] = scale * sum_k A[m,k] * B[n,k]  (+ bias[n])
// A: [M,K] row-major (lda=K), B: [N,K] row-major (ldb=K)
// Block computes a 128x128 tile at (blockIdx.y, blockIdx.x); 256 threads,
// each owning an 8x8 register tile. BK = 8. All dims assumed multiples.
// ---------------------------------------------------------------------------
__device__ __forceinline__ void gemm_nt_tile(
    const float* __restrict__ A, int lda,
    const float* __restrict__ B, int ldb,
    float* __restrict__ C, int ldc,
    int K, const float* __restrict__ bias, float scale)
{
    __shared__ float As[8][128];
    __shared__ float Bs[8][128];

    const int tid = threadIdx.x;
    const int tx  = tid & 15;         // 0..15  -> n group
    const int ty  = tid >> 4;         // 0..15  -> m group
    const int m0  = blockIdx.y * 128;
    const int n0  = blockIdx.x * 128;

    const int lrow = tid >> 1;        // 0..127
    const int lcol = (tid & 1) << 2;  // 0 or 4

    const float* Aptr = A + (size_t)(m0 + lrow) * lda + lcol;
    const float* Bptr = B + (size_t)(n0 + lrow) * ldb + lcol;

    float acc[8][8];
    #pragma unroll
    for (int i = 0; i < 8; i++)
        #pragma unroll
        for (int j = 0; j < 8; j++) acc[i][j] = 0.0f;

    for (int kt = 0; kt < K; kt += 8) {
        float4 a = *(const float4*)(Aptr + kt);
        float4 b = *(const float4*)(Bptr + kt);
        __syncthreads();
        As[lcol + 0][lrow] = a.x;  As[lcol + 1][lrow] = a.y;
        As[lcol + 2][lrow] = a.z;  As[lcol + 3][lrow] = a.w;
        Bs[lcol + 0][lrow] = b.x;  Bs[lcol + 1][lrow] = b.y;
        Bs[lcol + 2][lrow] = b.z;  Bs[lcol + 3][lrow] = b.w;
        __syncthreads();

        #pragma unroll
        for (int kk = 0; kk < 8; kk++) {
            float ar[8], br[8];
            *(float4*)(ar)     = *(const float4*)&As[kk][ty * 8];
            *(float4*)(ar + 4) = *(const float4*)&As[kk][ty * 8 + 4];
            *(float4*)(br)     = *(const float4*)&Bs[kk][tx * 8];
            *(float4*)(br + 4) = *(const float4*)&Bs[kk][tx * 8 + 4];
            #pragma unroll
            for (int i = 0; i < 8; i++)
                #pragma unroll
                for (int j = 0; j < 8; j++)
                    acc[i][j] = fmaf(ar[i], br[j], acc[i][j]);
        }
    }

    // epilogue
    float bvals[8];
    #pragma unroll
    for (int j = 0; j < 8; j++)
        bvals[j] = bias ? bias[n0 + tx * 8 + j] : 0.0f;

    #pragma unroll
    for (int i = 0; i < 8; i++) {
        float* crow = C + (size_t)(m0 + ty * 8 + i) * ldc + n0 + tx * 8;
        float4 c0, c1;
        c0.x = acc[i][0] * scale + bvals[0];
        c0.y = acc[i][1] * scale + bvals[1];
        c0.z = acc[i][2] * scale + bvals[2];
        c0.w = acc[i][3] * scale + bvals[3];
        c1.x = acc[i][4] * scale + bvals[4];
        c1.y = acc[i][5] * scale + bvals[5];
        c1.z = acc[i][6] * scale + bvals[6];
        c1.w = acc[i][7] * scale + bvals[7];
        *(float4*)(crow)     = c0;
        *(float4*)(crow + 4) = c1;
    }
}

// ---------------------------------------------------------------------------
// Tiled SGEMM (NN): C[m,n] = sum_k A[m,k] * B[k,n]
// A: [M,K] row-major (lda=K), B: [K,N] row-major (ldb=N)
// ---------------------------------------------------------------------------
__device__ __forceinline__ void gemm_nn_tile(
    const float* __restrict__ A, int lda,
    const float* __restrict__ B, int ldb,
    float* __restrict__ C, int ldc,
    int K)
{
    __shared__ float As[8][128];
    __shared__ float Bs[8][128];

    const int tid = threadIdx.x;
    const int tx  = tid & 15;
    const int ty  = tid >> 4;
    const int m0  = blockIdx.y * 128;
    const int n0  = blockIdx.x * 128;

    const int arow = tid >> 1;
    const int acol = (tid & 1) << 2;
    const int bkr  = tid >> 5;          // 0..7
    const int bnc  = (tid & 31) << 2;   // 0..124

    const float* Aptr = A + (size_t)(m0 + arow) * lda + acol;
    const float* Bptr = B + (size_t)bkr * ldb + n0 + bnc;

    float acc[8][8];
    #pragma unroll
    for (int i = 0; i < 8; i++)
        #pragma unroll
        for (int j = 0; j < 8; j++) acc[i][j] = 0.0f;

    for (int kt = 0; kt < K; kt += 8) {
        float4 a = *(const float4*)(Aptr + kt);
        float4 b = *(const float4*)(Bptr + (size_t)kt * ldb);
        __syncthreads();
        As[acol + 0][arow] = a.x;  As[acol + 1][arow] = a.y;
        As[acol + 2][arow] = a.z;  As[acol + 3][arow] = a.w;
        *(float4*)&Bs[bkr][bnc] = b;
        __syncthreads();

        #pragma unroll
        for (int kk = 0; kk < 8; kk++) {
            float ar[8], br[8];
            *(float4*)(ar)     = *(const float4*)&As[kk][ty * 8];
            *(float4*)(ar + 4) = *(const float4*)&As[kk][ty * 8 + 4];
            *(float4*)(br)     = *(const float4*)&Bs[kk][tx * 8];
            *(float4*)(br + 4) = *(const float4*)&Bs[kk][tx * 8 + 4];
            #pragma unroll
            for (int i = 0; i < 8; i++)
                #pragma unroll
                for (int j = 0; j < 8; j++)
                    acc[i][j] = fmaf(ar[i], br[j], acc[i][j]);
        }
    }

    #pragma unroll
    for (int i = 0; i < 8; i++) {
        float* crow = C + (size_t)(m0 + ty * 8 + i) * ldc + n0 + tx * 8;
        *(float4*)(crow)     = *(float4*)&acc[i][0];
        *(float4*)(crow + 4) = *(float4*)&acc[i][4];
    }
}

// ---------------------------------------------------------------------------
// Kernels
// ---------------------------------------------------------------------------
__global__ __launch_bounds__(256) void qkv_kernel(
    const float* __restrict__ X,
    const float* __restrict__ Wq, const float* __restrict__ bq,
    const float* __restrict__ Wk, const float* __restrict__ bk,
    const float* __restrict__ Wv, const float* __restrict__ bv)
{
    const float* W; const float* bias; float* O;
    if (blockIdx.z == 0)      { W = Wq; bias = bq; O = g_q; }
    else if (blockIdx.z == 1) { W = Wk; bias = bk; O = g_k; }
    else                      { W = Wv; bias = bv; O = g_v; }
    gemm_nt_tile(X, D_MODEL, W, D_MODEL, O, FF_DIM, D_MODEL, bias, 1.0f);
}

__global__ __launch_bounds__(256) void scores_kernel()
{
    const int b = blockIdx.z;
    const float* Q = g_q + (size_t)b * SEQ * FF_DIM;
    const float* K = g_k + (size_t)b * SEQ * FF_DIM;
    float*       S = g_s + (size_t)b * SEQ * SEQ;
    gemm_nt_tile(Q, FF_DIM, K, FF_DIM, S, SEQ, FF_DIM, nullptr, ATTN_SCALE);
}

__global__ __launch_bounds__(256) void softmax_kernel()
{
    const int row = blockIdx.x;                 // 0 .. M_TOTAL-1
    float* p = g_s + (size_t)row * SEQ;
    const int tid  = threadIdx.x;
    const int lane = tid & 31;
    const int wid  = tid >> 5;

    __shared__ float red[32];

    float v[8];
    #pragma unroll
    for (int i = 0; i < 8; i++) v[i] = p[tid + i * 256];

    // --- max reduce ---
    float m = v[0];
    #pragma unroll
    for (int i = 1; i < 8; i++) m = fmaxf(m, v[i]);
    #pragma unroll
    for (int o = 16; o > 0; o >>= 1) m = fmaxf(m, __shfl_xor_sync(0xffffffffu, m, o));
    if (lane == 0) red[wid] = m;
    __syncthreads();
    if (tid < 32) {
        float t = (lane < 8) ? red[lane] : -3.4e38f;
        #pragma unroll
        for (int o = 4; o > 0; o >>= 1) t = fmaxf(t, __shfl_xor_sync(0xffffffffu, t, o));
        red[lane] = t;   // all lanes write the same reduced value
    }
    __syncthreads();
    m = red[0];
    __syncthreads();

    // --- exp + sum reduce ---
    float s = 0.0f;
    #pragma unroll
    for (int i = 0; i < 8; i++) { v[i] = __expf(v[i] - m); s += v[i]; }
    #pragma unroll
    for (int o = 16; o > 0; o >>= 1) s += __shfl_xor_sync(0xffffffffu, s, o);
    if (lane == 0) red[wid] = s;
    __syncthreads();
    if (tid < 32) {
        float t = (lane < 8) ? red[lane] : 0.0f;
        #pragma unroll
        for (int o = 4; o > 0; o >>= 1) t += __shfl_xor_sync(0xffffffffu, t, o);
        red[lane] = t;
    }
    __syncthreads();
    const float inv = 1.0f / red[0];

    #pragma unroll
    for (int i = 0; i < 8; i++) p[tid + i * 256] = v[i] * inv;
}

__global__ __launch_bounds__(256) void pv_kernel(float* __restrict__ out)
{
    const int b = blockIdx.z;
    const float* P = g_s + (size_t)b * SEQ * SEQ;
    const float* V = g_v + (size_t)b * SEQ * FF_DIM;
    float*       O = out + (size_t)b * SEQ * FF_DIM;
    gemm_nn_tile(P, SEQ, V, FF_DIM, O, FF_DIM, SEQ);
}

// ---------------------------------------------------------------------------
// Entry point
// ---------------------------------------------------------------------------
extern "C" void kernel_launch(void* const* d_in, const int* in_sizes, int n_in,
                              void* d_out, int out_size)
{
    const float* seq = (const float*)d_in[0];
    const float* Wq  = (const float*)d_in[1];
    const float* bq  = (const float*)d_in[2];
    const float* Wk  = (const float*)d_in[3];
    const float* bk  = (const float*)d_in[4];
    const float* Wv  = (const float*)d_in[5];
    const float* bv  = (const float*)d_in[6];
    float* out = (float*)d_out;

    dim3 blk(256);

    // 1) Q/K/V projections: C = X @ W^T + b, fused across z
    qkv_kernel<<<dim3(FF_DIM / 128, M_TOTAL / 128, 3), blk>>>(
        seq, Wq, bq, Wk, bk, Wv, bv);

    // 2) scores = scale * Q @ K^T  (per batch)
    scores_kernel<<<dim3(SEQ / 128, SEQ / 128, BATCH), blk>>>();

    // 3) row softmax over the last dim
    softmax_kernel<<<M_TOTAL, 256>>>();

    // 4) out = P @ V (per batch)
    pv_kernel<<<dim3(FF_DIM / 128, SEQ / 128, BATCH), blk>>>(out);
}

// round 5
// speedup vs baseline: 2.5633x; 2.5633x over previous
#include <cuda_runtime.h>
#include <cstdint>
#include <cstddef>

#define D_MODEL 1024
#define FF_DIM  1024
#define BATCH   8
#define SEQ     2048
#define M_TOTAL (BATCH * SEQ)      // 16384
#define ATTN_SCALE 0.03125f

// ---- GEMM tile config ------------------------------------------------------
#define BM 128
#define BN 128
#define BK 32
#define AS_STRIDE 36                         // 32 data + 4 pad words -> conflict-free frags
#define TILE_WORDS (128 * AS_STRIDE)         // 4608 floats per operand tile
#define STAGE_WORDS (2 * TILE_WORDS)         // A + B
#define SMEM_WORDS  (2 * STAGE_WORDS)        // 2 stages
#define SMEM_BYTES  (SMEM_WORDS * 4)         // 73728 B

// ---- scratch (device globals; no runtime allocation) -----------------------
__device__ float g_x[(size_t)M_TOTAL * D_MODEL];          // rounded X
__device__ float g_w[3][(size_t)FF_DIM * D_MODEL];        // rounded Wq/Wk/Wv
__device__ float g_q[(size_t)M_TOTAL * FF_DIM];           // rounded Q (rna in epilogue)
__device__ float g_k[(size_t)M_TOTAL * FF_DIM];           // rounded K
__device__ float g_v[(size_t)M_TOTAL * FF_DIM];           // V (fp32)
__device__ float g_vT[(size_t)BATCH * FF_DIM * SEQ];      // rounded V^T
__device__ float g_s[(size_t)BATCH * SEQ * SEQ];          // scores / P

// ---- helpers ---------------------------------------------------------------
__device__ __forceinline__ uint32_t smem_u32(const void* p) {
    uint32_t a;
    asm("{ .reg .u64 t; cvta.to.shared.u64 t, %1; cvt.u32.u64 %0, t; }"
        : "=r"(a) : "l"(p));
    return a;
}

__device__ __forceinline__ float rna_tf32(float x) {
    uint32_t r; asm("cvt.rna.tf32.f32 %0, %1;" : "=r"(r) : "f"(x));
    return __uint_as_float(r);
}

__device__ __forceinline__ void cp_async16(uint32_t dst, const void* src) {
    asm volatile("cp.async.cg.shared.global [%0], [%1], 16;"
                 :: "r"(dst), "l"(src));
}
#define CP_COMMIT() asm volatile("cp.async.commit_group;" ::: "memory")
#define CP_WAIT(n)  asm volatile("cp.async.wait_group %0;" :: "n"(n) : "memory")

__device__ __forceinline__ void mma_tf32(float* d, const uint32_t* a, const uint32_t* b) {
    asm volatile(
        "mma.sync.aligned.m16n8k8.row.col.f32.tf32.tf32.f32 "
        "{%0,%1,%2,%3}, {%4,%5,%6,%7}, {%8,%9}, {%0,%1,%2,%3};"
        : "+f"(d[0]), "+f"(d[1]), "+f"(d[2]), "+f"(d[3])
        : "r"(a[0]), "r"(a[1]), "r"(a[2]), "r"(a[3]), "r"(b[0]), "r"(b[1]));
}

// ---------------------------------------------------------------------------
// tf32 tensor-core GEMM (NT): C[m,n] = scale * sum_k A[m,k]*B[n,k] + bias[n]
// A: [M,K] row-major, B: [N,K] row-major. 256 threads, 8 warps (2m x 4n),
// warp tile 64x32, 2-stage cp.async double buffer.
// ---------------------------------------------------------------------------
__device__ __forceinline__ void gemm_core(
    const float* __restrict__ A, int lda,
    const float* __restrict__ B, int ldb,
    float* __restrict__ C, int ldc,
    int K, const float* __restrict__ bias, float scale, bool do_round)
{
    extern __shared__ float smem[];
    const int tid  = threadIdx.x;
    const int wid  = tid >> 5;
    const int lane = tid & 31;
    const int wm   = wid >> 2;          // 0..1
    const int wn   = wid & 3;           // 0..3
    const int g    = lane >> 2;         // 0..7
    const int c    = lane & 3;          // 0..3
    const int m0   = blockIdx.y * BM;
    const int n0   = blockIdx.x * BN;
    const int NT   = K >> 5;

    float acc[4][4][4];
    #pragma unroll
    for (int i = 0; i < 4; i++)
        #pragma unroll
        for (int j = 0; j < 4; j++)
            #pragma unroll
            for (int r = 0; r < 4; r++) acc[i][j][r] = 0.0f;

    // producer mapping: 2 threads per 32-float row, each copies 16 floats (4x16B)
    const int prow = tid >> 1;
    const int pcol = (tid & 1) * 16;
    const float* Ag = A + (size_t)(m0 + prow) * lda + pcol;
    const float* Bg = B + (size_t)(n0 + prow) * ldb + pcol;
    const uint32_t sb = smem_u32(smem);
    const uint32_t a_dst = sb + (uint32_t)(prow * AS_STRIDE + pcol) * 4;
    const uint32_t b_dst = a_dst + TILE_WORDS * 4;

    // prologue: stage 0
    {
        #pragma unroll
        for (int j = 0; j < 4; j++) {
            cp_async16(a_dst + j * 16, Ag + j * 4);
            cp_async16(b_dst + j * 16, Bg + j * 4);
        }
        CP_COMMIT();
    }

    for (int t = 0; t < NT; t++) {
        if (t + 1 < NT) {
            const uint32_t so = (uint32_t)(((t + 1) & 1) * STAGE_WORDS) * 4;
            const float* ag = Ag + (t + 1) * BK;
            const float* bg = Bg + (t + 1) * BK;
            #pragma unroll
            for (int j = 0; j < 4; j++) {
                cp_async16(a_dst + so + j * 16, ag + j * 4);
                cp_async16(b_dst + so + j * 16, bg + j * 4);
            }
            CP_COMMIT();
            CP_WAIT(1);
        } else {
            CP_WAIT(0);
        }
        __syncthreads();

        const float* As = smem + (t & 1) * STAGE_WORDS;
        const float* Bs = As + TILE_WORDS;

        #pragma unroll
        for (int ks = 0; ks < 4; ks++) {
            const int kb = ks * 8;
            uint32_t af[4][4], bf[4][2];
            #pragma unroll
            for (int mt = 0; mt < 4; mt++) {
                const float* ap = As + (wm * 64 + mt * 16 + g) * AS_STRIDE + kb + c;
                af[mt][0] = __float_as_uint(ap[0]);
                af[mt][1] = __float_as_uint(ap[8 * AS_STRIDE]);
                af[mt][2] = __float_as_uint(ap[4]);
                af[mt][3] = __float_as_uint(ap[8 * AS_STRIDE + 4]);
            }
            #pragma unroll
            for (int nt = 0; nt < 4; nt++) {
                const float* bp = Bs + (wn * 32 + nt * 8 + g) * AS_STRIDE + kb + c;
                bf[nt][0] = __float_as_uint(bp[0]);
                bf[nt][1] = __float_as_uint(bp[4]);
            }
            #pragma unroll
            for (int mt = 0; mt < 4; mt++)
                #pragma unroll
                for (int nt = 0; nt < 4; nt++)
                    mma_tf32(acc[mt][nt], af[mt], bf[nt]);
        }
        __syncthreads();
    }

    // epilogue
    #pragma unroll
    for (int mt = 0; mt < 4; mt++) {
        #pragma unroll
        for (int nt = 0; nt < 4; nt++) {
            const int row0 = m0 + wm * 64 + mt * 16 + g;
            const int col  = n0 + wn * 32 + nt * 8 + 2 * c;
            const float b0 = bias ? bias[col]     : 0.0f;
            const float b1 = bias ? bias[col + 1] : 0.0f;
            #pragma unroll
            for (int h = 0; h < 2; h++) {
                float x0 = acc[mt][nt][2 * h + 0] * scale + b0;
                float x1 = acc[mt][nt][2 * h + 1] * scale + b1;
                if (do_round) { x0 = rna_tf32(x0); x1 = rna_tf32(x1); }
                float2 o; o.x = x0; o.y = x1;
                *(float2*)(C + (size_t)(row0 + h * 8) * ldc + col) = o;
            }
        }
    }
}

// ---------------------------------------------------------------------------
// GEMM entry kernels
// ---------------------------------------------------------------------------
__global__ __launch_bounds__(256, 2) void qkv_tc(
    const float* __restrict__ bq, const float* __restrict__ bk,
    const float* __restrict__ bv)
{
    const int z = blockIdx.z;
    const float* W = g_w[z];
    const float* bias = (z == 0) ? bq : (z == 1) ? bk : bv;
    float* O = (z == 0) ? g_q : (z == 1) ? g_k : g_v;
    gemm_core(g_x, D_MODEL, W, D_MODEL, O, FF_DIM, D_MODEL, bias, 1.0f, z < 2);
}

__global__ __launch_bounds__(256, 2) void scores_tc()
{
    const int b = blockIdx.z;
    gemm_core(g_q + (size_t)b * SEQ * FF_DIM, FF_DIM,
              g_k + (size_t)b * SEQ * FF_DIM, FF_DIM,
              g_s + (size_t)b * SEQ * SEQ,    SEQ,
              FF_DIM, nullptr, ATTN_SCALE, false);
}

__global__ __launch_bounds__(256, 2) void pv_tc(float* __restrict__ out)
{
    const int b = blockIdx.z;
    gemm_core(g_s  + (size_t)b * SEQ * SEQ,    SEQ,
              g_vT + (size_t)b * FF_DIM * SEQ, SEQ,
              out  + (size_t)b * SEQ * FF_DIM, FF_DIM,
              SEQ, nullptr, 1.0f, false);
}

// ---------------------------------------------------------------------------
// Prep: round X / W to tf32 (RN) into scratch
// ---------------------------------------------------------------------------
__global__ void round_kernel(const float* __restrict__ src, int which, int n4)
{
    float* dst = (which == 0) ? g_x : g_w[which - 1];
    int i = blockIdx.x * blockDim.x + threadIdx.x;
    if (i < n4) {
        float4 v = ((const float4*)src)[i];
        v.x = rna_tf32(v.x); v.y = rna_tf32(v.y);
        v.z = rna_tf32(v.z); v.w = rna_tf32(v.w);
        ((float4*)dst)[i] = v;
    }
}

// ---------------------------------------------------------------------------
// V transpose (per batch): g_vT[b][f][s] = rna(g_v[b][s][f])
// ---------------------------------------------------------------------------
__global__ void transpose_v()
{
    __shared__ float t[32][33];
    const int b  = blockIdx.z;
    const int s0 = blockIdx.x * 32;
    const int f0 = blockIdx.y * 32;
    const int tx = threadIdx.x, ty = threadIdx.y;

    #pragma unroll
    for (int i = 0; i < 4; i++) {
        int s = s0 + ty + i * 8;
        t[ty + i * 8][tx] = g_v[((size_t)b * SEQ + s) * FF_DIM + f0 + tx];
    }
    __syncthreads();
    #pragma unroll
    for (int i = 0; i < 4; i++) {
        int f = f0 + ty + i * 8;
        g_vT[((size_t)b * FF_DIM + f) * SEQ + s0 + tx] = rna_tf32(t[tx][ty + i * 8]);
    }
}

// ---------------------------------------------------------------------------
// Row softmax over g_s rows (len 2048), output rounded to tf32
// ---------------------------------------------------------------------------
__global__ __launch_bounds__(256) void softmax_kernel()
{
    const int row = blockIdx.x;
    float* p = g_s + (size_t)row * SEQ;
    const int tid  = threadIdx.x;
    const int lane = tid & 31;
    const int wid  = tid >> 5;
    __shared__ float red[32];

    float v[8];
    #pragma unroll
    for (int i = 0; i < 8; i++) v[i] = p[tid + i * 256];

    float m = v[0];
    #pragma unroll
    for (int i = 1; i < 8; i++) m = fmaxf(m, v[i]);
    #pragma unroll
    for (int o = 16; o > 0; o >>= 1) m = fmaxf(m, __shfl_xor_sync(0xffffffffu, m, o));
    if (lane == 0) red[wid] = m;
    __syncthreads();
    if (tid < 32) {
        float t = (lane < 8) ? red[lane] : -3.4e38f;
        #pragma unroll
        for (int o = 4; o > 0; o >>= 1) t = fmaxf(t, __shfl_xor_sync(0xffffffffu, t, o));
        red[lane] = t;
    }
    __syncthreads();
    m = red[0];
    __syncthreads();

    float s = 0.0f;
    #pragma unroll
    for (int i = 0; i < 8; i++) { v[i] = __expf(v[i] - m); s += v[i]; }
    #pragma unroll
    for (int o = 16; o > 0; o >>= 1) s += __shfl_xor_sync(0xffffffffu, s, o);
    if (lane == 0) red[wid] = s;
    __syncthreads();
    if (tid < 32) {
        float t = (lane < 8) ? red[lane] : 0.0f;
        #pragma unroll
        for (int o = 4; o > 0; o >>= 1) t += __shfl_xor_sync(0xffffffffu, t, o);
        red[lane] = t;
    }
    __syncthreads();
    const float inv = 1.0f / red[0];

    #pragma unroll
    for (int i = 0; i < 8; i++) p[tid + i * 256] = rna_tf32(v[i] * inv);
}

// ---------------------------------------------------------------------------
// Entry point
// ---------------------------------------------------------------------------
extern "C" void kernel_launch(void* const* d_in, const int* in_sizes, int n_in,
                              void* d_out, int out_size)
{
    const float* seq = (const float*)d_in[0];
    const float* Wq  = (const float*)d_in[1];
    const float* bq  = (const float*)d_in[2];
    const float* Wk  = (const float*)d_in[3];
    const float* bk  = (const float*)d_in[4];
    const float* Wv  = (const float*)d_in[5];
    const float* bv  = (const float*)d_in[6];
    float* out = (float*)d_out;

    // idempotent every call (no static guards allowed)
    cudaFuncSetAttribute(qkv_tc,    cudaFuncAttributeMaxDynamicSharedMemorySize, SMEM_BYTES);
    cudaFuncSetAttribute(scores_tc, cudaFuncAttributeMaxDynamicSharedMemorySize, SMEM_BYTES);
    cudaFuncSetAttribute(pv_tc,     cudaFuncAttributeMaxDynamicSharedMemorySize, SMEM_BYTES);

    // 1) round inputs to tf32 (RN)
    const int nx4 = (M_TOTAL * D_MODEL) / 4;
    const int nw4 = (FF_DIM * D_MODEL) / 4;
    round_kernel<<<(nx4 + 255) / 256, 256>>>(seq, 0, nx4);
    round_kernel<<<(nw4 + 255) / 256, 256>>>(Wq, 1, nw4);
    round_kernel<<<(nw4 + 255) / 256, 256>>>(Wk, 2, nw4);
    round_kernel<<<(nw4 + 255) / 256, 256>>>(Wv, 3, nw4);

    // 2) Q/K/V projections (tensor core)
    qkv_tc<<<dim3(FF_DIM / BN, M_TOTAL / BM, 3), 256, SMEM_BYTES>>>(bq, bk, bv);

    // 3) V^T (rounded) for the PV GEMM
    transpose_v<<<dim3(SEQ / 32, FF_DIM / 32, BATCH), dim3(32, 8)>>>();

    // 4) scores = scale * Q K^T
    scores_tc<<<dim3(SEQ / BN, SEQ / BM, BATCH), 256, SMEM_BYTES>>>();

    // 5) softmax (rounded output)
    softmax_kernel<<<M_TOTAL, 256>>>();

    // 6) out = P V
    pv_tc<<<dim3(FF_DIM / BN, SEQ / BM, BATCH), 256, SMEM_BYTES>>>(out);
}